// round 15
// baseline (speedup 1.0000x reference)
#include <cuda_runtime.h>
#include <cuda_fp16.h>
#include <cstdint>

// ---------------------------------------------------------------------------
// TernaryConv2d via mma.sync m16n8k16 (HMMA fp16, fp32 accum) implicit GEMM.
// Warp tile M=64 (4 mtiles): each B pair feeds 4 HMMAs. 256-thr CTA covering
// 4 output rows (A-STS amortized 2x), FORCED 2 CTAs/SM, 2-stage pipeline.
// x: [32,128,56,56] f32, w: [256,128,3,3] f32, bias:[256] -> out:[32,256,54,54]
// ---------------------------------------------------------------------------

#define CC    128
#define HHH   56
#define WID   56
#define OCH   256
#define OHH   54
#define OWW   54
#define NN    32

#define NTHR   256
#define ICK    16           // ic per chunk (one k16 HMMA deep)
#define NCHUNK 8
#define BROWS  6            // 4 out rows + 2 halo
#define BCOLS  68           // row stride in half2 words
#define PLX    424          // per-icpair plane stride (424%32=8 -> bank perm 8*t4+g)
#define A_WORDS_CHUNK (9 * 8 * 32 * 4)         // 9216 words = 36864 B
#define A_BYTES_CHUNK (A_WORDS_CHUNK * 4)
#define B_WORDS       (8 * PLX)                // 3392 words = 13568 B
#define STAGE_BYTES   (A_BYTES_CHUNK + B_WORDS * 4)    // 50432
#define SMEM_DYN      (2 * STAGE_BYTES)                // 100864 (x2 CTAs = 201.7KB/SM)

__device__ __align__(16) uint32_t g_qw[2 * NCHUNK * A_WORDS_CHUNK];
__device__ __align__(16) uint32_t g_xh[NN * 64 * HHH * WID];   // half2 planes
__device__ unsigned g_wmax_bits;

// ------------------------- preprocessing ----------------------------------
__global__ void k_init() { g_wmax_bits = 0u; }

__global__ void k_max(const float* __restrict__ w, int n) {
    float m = 0.f;
    for (int i = blockIdx.x * blockDim.x + threadIdx.x; i < n; i += gridDim.x * blockDim.x)
        m = fmaxf(m, fabsf(w[i]));
#pragma unroll
    for (int o = 16; o > 0; o >>= 1) m = fmaxf(m, __shfl_xor_sync(~0u, m, o));
    __shared__ float sm[32];
    int lane = threadIdx.x & 31, wd = threadIdx.x >> 5;
    if (lane == 0) sm[wd] = m;
    __syncthreads();
    if (threadIdx.x < 32) {
        int nw = (blockDim.x + 31) >> 5;
        m = (threadIdx.x < nw) ? sm[threadIdx.x] : 0.f;
#pragma unroll
        for (int o = 16; o > 0; o >>= 1) m = fmaxf(m, __shfl_xor_sync(~0u, m, o));
        if (threadIdx.x == 0) atomicMax(&g_wmax_bits, __float_as_uint(m));
    }
}

// quantize weights into m16n8k16 A-fragment order, half2-packed:
// word idx = ((half*8+chunk)*72 + tap*8 + mtile)*128 + lane*4 + r
__global__ void k_quant(const float* __restrict__ w) {
    int idx = blockIdx.x * blockDim.x + threadIdx.x;
    if (idx >= 2 * NCHUNK * A_WORDS_CHUNK) return;
    int r     = idx & 3;
    int lane  = (idx >> 2) & 31;
    int f     = idx >> 7;
    int mtile = f & 7;
    int tap   = (f >> 3) % 9;
    int hc    = f / 72;
    int half  = hc >> 3, chunk = hc & 7;
    int g  = lane >> 2, t4 = lane & 3;
    int oc  = half * 128 + mtile * 16 + g + 8 * (r & 1);
    int ic0 = chunk * ICK + 2 * t4 + 8 * (r >> 1);
    float t = 0.05f * __uint_as_float(g_wmax_bits);
    float w0 = w[(oc * CC + ic0) * 9 + tap];
    float w1 = w[(oc * CC + ic0 + 1) * 9 + tap];
    __half h0 = __float2half_rn((w0 > t ? 1.f : 0.f) - (w0 < -t ? 1.f : 0.f));
    __half h1 = __float2half_rn((w1 > t ? 1.f : 0.f) - (w1 < -t ? 1.f : 0.f));
    g_qw[idx] = (uint32_t)__half_as_ushort(h0) | ((uint32_t)__half_as_ushort(h1) << 16);
}

// x -> channel-pair packed half2 planes, vectorized 4 cols/thread
__global__ void k_xh(const float* __restrict__ x) {
    int idx = blockIdx.x * blockDim.x + threadIdx.x;   // over NN*64*HHH*14
    if (idx >= NN * 64 * HHH * 14) return;
    int c4  = idx % 14;
    int h   = (idx / 14) % HHH;
    int icp = (idx / (14 * HHH)) & 63;
    int n   = idx / (14 * HHH * 64);
    const float* p = x + ((size_t)(n * CC + icp * 2) * HHH + h) * WID + c4 * 4;
    float4 a = *(const float4*)p;
    float4 b = *(const float4*)(p + HHH * WID);
    uint4 o;
    o.x = (uint32_t)__half_as_ushort(__float2half_rn(a.x)) | ((uint32_t)__half_as_ushort(__float2half_rn(b.x)) << 16);
    o.y = (uint32_t)__half_as_ushort(__float2half_rn(a.y)) | ((uint32_t)__half_as_ushort(__float2half_rn(b.y)) << 16);
    o.z = (uint32_t)__half_as_ushort(__float2half_rn(a.z)) | ((uint32_t)__half_as_ushort(__float2half_rn(b.z)) << 16);
    o.w = (uint32_t)__half_as_ushort(__float2half_rn(a.w)) | ((uint32_t)__half_as_ushort(__float2half_rn(b.w)) << 16);
    *(uint4*)(g_xh + ((size_t)(n * 64 + icp) * HHH + h) * WID + c4 * 4) = o;
}

// ------------------------- helpers -----------------------------------------
__device__ __forceinline__ void mma16(float* c, const uint4& a, uint32_t b0, uint32_t b1) {
    asm volatile(
        "mma.sync.aligned.m16n8k16.row.col.f32.f16.f16.f32 "
        "{%0,%1,%2,%3}, {%4,%5,%6,%7}, {%8,%9}, {%0,%1,%2,%3};"
        : "+f"(c[0]), "+f"(c[1]), "+f"(c[2]), "+f"(c[3])
        : "r"(a.x), "r"(a.y), "r"(a.z), "r"(a.w), "r"(b0), "r"(b1));
}

__device__ __forceinline__ uint32_t smem_u32(const void* p) {
    uint32_t a;
    asm("{ .reg .u64 t; cvta.to.shared.u64 t, %1; cvt.u32.u64 %0, t; }" : "=r"(a) : "l"(p));
    return a;
}

__device__ __forceinline__ void cpa16(uint32_t dst, const void* src) {
    asm volatile("cp.async.cg.shared.global [%0], [%1], 16;" :: "r"(dst), "l"(src) : "memory");
}
__device__ __forceinline__ void cpa16_p(uint32_t dst, const void* src, int sz) {
    asm volatile("cp.async.cg.shared.global [%0], [%1], 16, %2;"
                 :: "r"(dst), "l"(src), "r"(sz) : "memory");
}

// issue all cp.async for one ic-chunk into stage buffer at smem addr `sbase`
__device__ __forceinline__ void stage_chunk(uint32_t sbase, int chunk, int half,
                                            int rg, int n, int tid) {
    // A: 2304 x 16B, linear, 9 per thread
    const uint4* asrc = (const uint4*)(g_qw + (size_t)(half * NCHUNK + chunk) * A_WORDS_CHUNK);
#pragma unroll
    for (int i = 0; i < 9; i++) {
        int e = i * NTHR + tid;
        cpa16(sbase + e * 16, asrc + e);
    }
    // B: 8 icpair x 6 rows x 14 x 16B; zero-fill rows beyond input (rg=13)
    const uint32_t bdst = sbase + A_BYTES_CHUNK;
#pragma unroll
    for (int it = 0; it < 3; it++) {
        int i = it * NTHR + tid;
        if (i < 8 * BROWS * 14) {
            int c4  = i % 14;
            int row = (i / 14) % BROWS;
            int icp = i / (14 * BROWS);
            int h   = rg * 4 + row;
            const uint32_t* s = g_xh + ((size_t)(n * 64 + chunk * 8 + icp) * HHH + h) * WID + c4 * 4;
            cpa16_p(bdst + (icp * PLX + row * BCOLS + c4 * 4) * 4, s, (h < HHH) ? 16 : 0);
        }
    }
    asm volatile("cp.async.commit_group;" ::: "memory");
}

// ------------------------- conv kernel --------------------------------------
// grid (2 oc-halves, 14 row-groups, 32 n), block 256 (warp_m 0..1, warp_n 0..3)
__global__ __launch_bounds__(NTHR, 2) void k_conv(const float* __restrict__ bias,
                                                  float* __restrict__ out) {
    extern __shared__ char smem[];
    const uint32_t sb = smem_u32(smem);

    const int tid    = threadIdx.x;
    const int wid    = tid >> 5;
    const int lane   = tid & 31;
    const int warp_m = wid & 1;       // 64-oc group (4 mtiles)
    const int warp_n = wid >> 1;      // 0..3 output rows
    const int g      = lane >> 2;
    const int t4     = lane & 3;
    const int half   = blockIdx.x;
    const int rg     = blockIdx.y;
    const int n      = blockIdx.z;

    // one-time zero of both B regions (pad cols + plane pad stay zero)
    for (int s = 0; s < 2; s++) {
        uint32_t* B = (uint32_t*)(smem + s * STAGE_BYTES + A_BYTES_CHUNK);
        for (int i = tid; i < B_WORDS; i += NTHR) B[i] = 0;
    }
    __syncthreads();

    float acc[4][7][4];
#pragma unroll
    for (int mi = 0; mi < 4; mi++)
#pragma unroll
        for (int ni = 0; ni < 7; ni++)
#pragma unroll
            for (int r = 0; r < 4; r++) acc[mi][ni][r] = 0.f;

    stage_chunk(sb, 0, half, rg, n, tid);

    for (int chunk = 0; chunk < NCHUNK; chunk++) {
        asm volatile("cp.async.wait_group 0;" ::: "memory");
        __syncthreads();
        if (chunk + 1 < NCHUNK)
            stage_chunk(sb + ((chunk + 1) & 1) * STAGE_BYTES, chunk + 1, half, rg, n, tid);

        const char*     stg = smem + (chunk & 1) * STAGE_BYTES;
        const uint4*    Af  = (const uint4*)stg;
        const uint32_t* Bs  = (const uint32_t*)(stg + A_BYTES_CHUNK);
        const uint32_t* Bq0 = Bs + t4 * PLX;          // k pair t4
        const uint32_t* Bq1 = Bs + (t4 + 4) * PLX;    // k pair t4+4

#pragma unroll
        for (int tap = 0; tap < 9; tap++) {
            const int kh = tap / 3, kw = tap - 3 * kh;
            const int prow = (warp_n + kh) * BCOLS + g + kw;
            const int fbase = (tap * 8 + warp_m * 4) * 32 + lane;
            const uint4 A0 = Af[fbase];
            const uint4 A1 = Af[fbase + 32];
            const uint4 A2 = Af[fbase + 64];
            const uint4 A3 = Af[fbase + 96];
            const uint32_t* B0 = Bq0 + prow;
            const uint32_t* B1 = Bq1 + prow;
#pragma unroll
            for (int ni = 0; ni < 7; ni++) {
                uint32_t b0 = B0[ni * 8];
                uint32_t b1 = B1[ni * 8];
                mma16(acc[0][ni], A0, b0, b1);
                mma16(acc[1][ni], A1, b0, b1);
                mma16(acc[2][ni], A2, b0, b1);
                mma16(acc[3][ni], A3, b0, b1);
            }
        }
    }

    // ---- epilogue
    const int oh = rg * 4 + warp_n;
    if (oh < OHH) {
#pragma unroll
        for (int mi = 0; mi < 4; mi++) {
            const int oc0 = half * 128 + warp_m * 64 + mi * 16 + g;
            const float bv0 = bias[oc0];
            const float bv1 = bias[oc0 + 8];
            float* o0 = out + ((size_t)n * OCH + oc0) * (OHH * OWW) + oh * OWW;
            float* o1 = o0 + 8 * (OHH * OWW);
#pragma unroll
            for (int ni = 0; ni < 7; ni++) {
                const int ow = ni * 8 + 2 * t4;
                if (ow < OWW) {
                    float2 v0 = make_float2(acc[mi][ni][0] + bv0, acc[mi][ni][1] + bv0);
                    float2 v1 = make_float2(acc[mi][ni][2] + bv1, acc[mi][ni][3] + bv1);
                    *(float2*)(o0 + ow) = v0;
                    *(float2*)(o1 + ow) = v1;
                }
            }
        }
    }
}

// ------------------------- launch -------------------------------------------
extern "C" void kernel_launch(void* const* d_in, const int* in_sizes, int n_in,
                              void* d_out, int out_size) {
    const float* x    = (const float*)d_in[0];
    const float* w    = (const float*)d_in[1];
    const float* bias = (const float*)d_in[2];
    float*       out  = (float*)d_out;

    k_init<<<1, 1>>>();
    k_max<<<256, 256>>>(w, OCH * CC * 9);
    k_xh<<<(NN * 64 * HHH * 14 + 255) / 256, 256>>>(x);
    k_quant<<<(2 * NCHUNK * A_WORDS_CHUNK + 255) / 256, 256>>>(w);

    cudaFuncSetAttribute(k_conv, cudaFuncAttributeMaxDynamicSharedMemorySize, SMEM_DYN);
    dim3 grid(2, 14, NN);
    k_conv<<<grid, NTHR, SMEM_DYN>>>(bias, out);

    (void)in_sizes; (void)n_in; (void)out_size;
}

// round 16
// speedup vs baseline: 1.1891x; 1.1891x over previous
#include <cuda_runtime.h>
#include <cuda_fp16.h>
#include <cstdint>

// ---------------------------------------------------------------------------
// TernaryConv2d via mma.sync m16n8k16 (HMMA fp16, fp32 accum) implicit GEMM.
// B (input) staged ONCE in smem (all 8 ic-chunks, 71.7KB, no mainloop barriers);
// A (ternary weights) streamed L2->regs with 2-deep prefetch (4-buffer ring).
// Warp tile M=64 x N=56. 128-thr CTAs, 2 CTAs/SM.
// x: [32,128,56,56] f32, w: [256,128,3,3] f32, bias:[256] -> out:[32,256,54,54]
// ---------------------------------------------------------------------------

#define CC    128
#define HHH   56
#define WID   56
#define OCH   256
#define OHH   54
#define OWW   54
#define NN    32

#define NTHR   128
#define NCHUNK 8
#define BROWS  4            // 2 out rows + 2 halo (always in-bounds: rg<=26)
#define BCOLS  68           // row stride in half2 words
#define PLX    280          // per-icpair plane stride (280%32=24 -> bank perm)
#define CHW    2240         // words per chunk = 8*PLX
#define B_WORDS (NCHUNK * CHW)              // 17920 words = 71680 B
#define SMEM_DYN (B_WORDS * 4)              // x2 CTAs = 143KB/SM

// A layout: uint4 index = ((half*9+tap)*8+chunk)*256 + (mtile*32) + lane
#define A_U4_HALF (9 * 8 * 8 * 32)          // 18432 uint4 per half

__device__ __align__(16) uint32_t g_qw[2 * A_U4_HALF * 4];
__device__ __align__(16) uint32_t g_xh[NN * 64 * HHH * WID];   // half2 planes
__device__ unsigned g_wmax_bits;

// ------------------------- preprocessing ----------------------------------
__global__ void k_init() { g_wmax_bits = 0u; }

__global__ void k_max(const float* __restrict__ w, int n) {
    float m = 0.f;
    for (int i = blockIdx.x * blockDim.x + threadIdx.x; i < n; i += gridDim.x * blockDim.x)
        m = fmaxf(m, fabsf(w[i]));
#pragma unroll
    for (int o = 16; o > 0; o >>= 1) m = fmaxf(m, __shfl_xor_sync(~0u, m, o));
    __shared__ float sm[32];
    int lane = threadIdx.x & 31, wd = threadIdx.x >> 5;
    if (lane == 0) sm[wd] = m;
    __syncthreads();
    if (threadIdx.x < 32) {
        int nw = (blockDim.x + 31) >> 5;
        m = (threadIdx.x < nw) ? sm[threadIdx.x] : 0.f;
#pragma unroll
        for (int o = 16; o > 0; o >>= 1) m = fmaxf(m, __shfl_xor_sync(~0u, m, o));
        if (threadIdx.x == 0) atomicMax(&g_wmax_bits, __float_as_uint(m));
    }
}

// quantize weights into m16n8k16 A-fragment order, half2-packed:
// word idx = ((((half*9+tap)*8+chunk)*8+mtile)*32 + lane)*4 + r
__global__ void k_quant(const float* __restrict__ w) {
    int idx = blockIdx.x * blockDim.x + threadIdx.x;
    if (idx >= 2 * A_U4_HALF * 4) return;
    int r     = idx & 3;
    int lane  = (idx >> 2) & 31;
    int mtile = (idx >> 7) & 7;
    int chunk = (idx >> 10) & 7;
    int f     = idx >> 13;            // half*9 + tap
    int tap   = f % 9;
    int half  = f / 9;
    int g  = lane >> 2, t4 = lane & 3;
    int oc  = half * 128 + mtile * 16 + g + 8 * (r & 1);
    int ic0 = chunk * 16 + 2 * t4 + 8 * (r >> 1);
    float t = 0.05f * __uint_as_float(g_wmax_bits);
    float w0 = w[(oc * CC + ic0) * 9 + tap];
    float w1 = w[(oc * CC + ic0 + 1) * 9 + tap];
    __half h0 = __float2half_rn((w0 > t ? 1.f : 0.f) - (w0 < -t ? 1.f : 0.f));
    __half h1 = __float2half_rn((w1 > t ? 1.f : 0.f) - (w1 < -t ? 1.f : 0.f));
    g_qw[idx] = (uint32_t)__half_as_ushort(h0) | ((uint32_t)__half_as_ushort(h1) << 16);
}

// x -> channel-pair packed half2 planes, vectorized 4 cols/thread
__global__ void k_xh(const float* __restrict__ x) {
    int idx = blockIdx.x * blockDim.x + threadIdx.x;   // over NN*64*HHH*14
    if (idx >= NN * 64 * HHH * 14) return;
    int c4  = idx % 14;
    int h   = (idx / 14) % HHH;
    int icp = (idx / (14 * HHH)) & 63;
    int n   = idx / (14 * HHH * 64);
    const float* p = x + ((size_t)(n * CC + icp * 2) * HHH + h) * WID + c4 * 4;
    float4 a = *(const float4*)p;
    float4 b = *(const float4*)(p + HHH * WID);
    uint4 o;
    o.x = (uint32_t)__half_as_ushort(__float2half_rn(a.x)) | ((uint32_t)__half_as_ushort(__float2half_rn(b.x)) << 16);
    o.y = (uint32_t)__half_as_ushort(__float2half_rn(a.y)) | ((uint32_t)__half_as_ushort(__float2half_rn(b.y)) << 16);
    o.z = (uint32_t)__half_as_ushort(__float2half_rn(a.z)) | ((uint32_t)__half_as_ushort(__float2half_rn(b.z)) << 16);
    o.w = (uint32_t)__half_as_ushort(__float2half_rn(a.w)) | ((uint32_t)__half_as_ushort(__float2half_rn(b.w)) << 16);
    *(uint4*)(g_xh + ((size_t)(n * 64 + icp) * HHH + h) * WID + c4 * 4) = o;
}

// ------------------------- helpers -----------------------------------------
__device__ __forceinline__ void mma16(float* c, const uint4& a, uint32_t b0, uint32_t b1) {
    asm volatile(
        "mma.sync.aligned.m16n8k16.row.col.f32.f16.f16.f32 "
        "{%0,%1,%2,%3}, {%4,%5,%6,%7}, {%8,%9}, {%0,%1,%2,%3};"
        : "+f"(c[0]), "+f"(c[1]), "+f"(c[2]), "+f"(c[3])
        : "r"(a.x), "r"(a.y), "r"(a.z), "r"(a.w), "r"(b0), "r"(b1));
}

__device__ __forceinline__ uint32_t smem_u32(const void* p) {
    uint32_t a;
    asm("{ .reg .u64 t; cvta.to.shared.u64 t, %1; cvt.u32.u64 %0, t; }" : "=r"(a) : "l"(p));
    return a;
}

__device__ __forceinline__ void cpa16(uint32_t dst, const void* src) {
    asm volatile("cp.async.cg.shared.global [%0], [%1], 16;" :: "r"(dst), "l"(src) : "memory");
}

// ------------------------- conv kernel --------------------------------------
// grid (2 oc-halves, 27 row-groups, 32 n), block 128 (warp_m 0..1, warp_n 0..1)
__global__ __launch_bounds__(NTHR, 2) void k_conv(const float* __restrict__ bias,
                                                  float* __restrict__ out) {
    extern __shared__ char smem[];
    const uint32_t sb = smem_u32(smem);

    const int tid    = threadIdx.x;
    const int wid    = tid >> 5;
    const int lane   = tid & 31;
    const int warp_m = wid & 1;       // 64-oc group (4 mtiles)
    const int warp_n = wid >> 1;      // 0..1 output rows
    const int g      = lane >> 2;
    const int t4     = lane & 3;
    const int half   = blockIdx.x;
    const int rg     = blockIdx.y;
    const int n      = blockIdx.z;

    // zero all of B (pad cols + plane tails), then stage all 8 chunks once
    for (int i = tid; i < B_WORDS / 4; i += NTHR)
        ((uint4*)smem)[i] = make_uint4(0, 0, 0, 0);
    __syncthreads();
    {
#pragma unroll
        for (int it = 0; it < 28; it++) {
            int i = it * NTHR + tid;
            int c4    = i % 14;
            int row   = (i / 14) & 3;
            int icp   = (i / 56) & 7;
            int chunk = i / 448;
            const uint32_t* s = g_xh + ((size_t)(n * 64 + chunk * 8 + icp) * HHH
                                        + (rg * 2 + row)) * WID + c4 * 4;
            cpa16(sb + (chunk * CHW + icp * PLX + row * BCOLS + c4 * 4) * 4, s);
        }
        asm volatile("cp.async.commit_group;" ::: "memory");
    }

    float acc[4][7][4];
#pragma unroll
    for (int mi = 0; mi < 4; mi++)
#pragma unroll
        for (int ni = 0; ni < 7; ni++)
#pragma unroll
            for (int r = 0; r < 4; r++) acc[mi][ni][r] = 0.f;

    // A stream base for this warp: uint4 units
    const uint4* Ag = (const uint4*)g_qw + (size_t)half * A_U4_HALF + warp_m * 128 + lane;

    // prologue: prefetch A for flat iterations 0 and 1 (4-buffer ring, depth 2)
    uint4 abuf[4][4];
#pragma unroll
    for (int j = 0; j < 4; j++) abuf[0][j] = __ldg(Ag + j * 32);
#pragma unroll
    for (int j = 0; j < 4; j++) abuf[1][j] = __ldg(Ag + 256 + j * 32);

    asm volatile("cp.async.wait_group 0;" ::: "memory");
    __syncthreads();

    const uint32_t* Bs = (const uint32_t*)smem;

    for (int tap = 0; tap < 9; tap++) {
        const int kh = tap / 3, kw = tap - 3 * kh;
        const int prow = (warp_n + kh) * BCOLS + g + kw;
        const uint32_t* Bt0 = Bs + t4 * PLX + prow;          // + chunk*CHW
        const uint32_t* Bt1 = Bt0 + 4 * PLX;
#pragma unroll
        for (int chunk = 0; chunk < 8; chunk++) {
            // prefetch flat iteration it+2 (phase (chunk+2)&3: tap*8 ≡ 0 mod 4)
            const int nidx = tap * 8 + chunk + 2;
            if (nidx < 72) {
                const uint4* An = Ag + (size_t)nidx * 256;
#pragma unroll
                for (int j = 0; j < 4; j++) abuf[(chunk + 2) & 3][j] = __ldg(An + j * 32);
            }
            const uint4* A = abuf[chunk & 3];
            const uint32_t* B0 = Bt0 + chunk * CHW;
            const uint32_t* B1 = Bt1 + chunk * CHW;
#pragma unroll
            for (int ni = 0; ni < 7; ni++) {
                uint32_t b0 = B0[ni * 8];
                uint32_t b1 = B1[ni * 8];
                mma16(acc[0][ni], A[0], b0, b1);
                mma16(acc[1][ni], A[1], b0, b1);
                mma16(acc[2][ni], A[2], b0, b1);
                mma16(acc[3][ni], A[3], b0, b1);
            }
        }
    }

    // ---- epilogue (oh = rg*2 + warp_n, always < 54)
    const int oh = rg * 2 + warp_n;
#pragma unroll
    for (int mi = 0; mi < 4; mi++) {
        const int oc0 = half * 128 + warp_m * 64 + mi * 16 + g;
        const float bv0 = bias[oc0];
        const float bv1 = bias[oc0 + 8];
        float* o0 = out + ((size_t)n * OCH + oc0) * (OHH * OWW) + oh * OWW;
        float* o1 = o0 + 8 * (OHH * OWW);
#pragma unroll
        for (int ni = 0; ni < 7; ni++) {
            const int ow = ni * 8 + 2 * t4;
            if (ow < OWW) {
                float2 v0 = make_float2(acc[mi][ni][0] + bv0, acc[mi][ni][1] + bv0);
                float2 v1 = make_float2(acc[mi][ni][2] + bv1, acc[mi][ni][3] + bv1);
                *(float2*)(o0 + ow) = v0;
                *(float2*)(o1 + ow) = v1;
            }
        }
    }
}

// ------------------------- launch -------------------------------------------
extern "C" void kernel_launch(void* const* d_in, const int* in_sizes, int n_in,
                              void* d_out, int out_size) {
    const float* x    = (const float*)d_in[0];
    const float* w    = (const float*)d_in[1];
    const float* bias = (const float*)d_in[2];
    float*       out  = (float*)d_out;

    k_init<<<1, 1>>>();
    k_max<<<256, 256>>>(w, OCH * CC * 9);
    k_xh<<<(NN * 64 * HHH * 14 + 255) / 256, 256>>>(x);
    k_quant<<<(2 * A_U4_HALF * 4 + 255) / 256, 256>>>(w);

    cudaFuncSetAttribute(k_conv, cudaFuncAttributeMaxDynamicSharedMemorySize, SMEM_DYN);
    dim3 grid(2, 27, NN);
    k_conv<<<grid, NTHR, SMEM_DYN>>>(bias, out);

    (void)in_sizes; (void)n_in; (void)out_size;
}

// round 17
// speedup vs baseline: 1.6508x; 1.3883x over previous
#include <cuda_runtime.h>
#include <cuda_fp16.h>
#include <cstdint>

// ---------------------------------------------------------------------------
// TernaryConv2d via mma.sync m16n8k16 (HMMA fp16, fp32 accum) implicit GEMM.
// Ternary weights stored as BYTE CODES (w+1 in {0,1,2}) in smem: half the A
// smem volume; expanded to exact fp16 via PRMT(0x64..)+add.f16x2(-1025).
// Warp tile M=64 x N=56, 128-thr CTAs, 2 CTAs/SM, 3-stage cp.async pipeline.
// x: [32,128,56,56] f32, w: [256,128,3,3] f32, bias:[256] -> out:[32,256,54,54]
// ---------------------------------------------------------------------------

#define CC    128
#define HHH   56
#define WID   56
#define OCH   256
#define OHH   54
#define OWW   54
#define NN    32

#define NTHR   128
#define NCHUNK 8
#define BROWS  4            // 2 out rows + 2 halo (always in-bounds: rg<=26)
#define BCOLS  68           // row stride in half2 words
#define PLX    280          // per-icpair plane stride (280%32=24 -> bank perm)
#define A_BYTES_CHUNK (9 * 4 * 32 * 16)        // taps x mp x lanes x 16B = 18432
#define B_WORDS       (8 * PLX)                // 2240 words = 8960 B
#define STAGE_BYTES   (A_BYTES_CHUNK + B_WORDS * 4)    // 27392
#define NSTAGE 3
#define SMEM_DYN      (NSTAGE * STAGE_BYTES)           // 82176 (x2 CTAs = 164KB/SM)

// code layout: uint32 idx = ((((half*8+chunk)*9+tap)*4+mp)*32+lane)*4 + q
//   q0=cuA(mtile=2mp) q1=cuB(2mp) q2=cuA(2mp+1) q3=cuB(2mp+1)
//   cuA bytes=[c(g,klo0),c(g,klo1),c(g+8,klo0),c(g+8,klo1)], cuB same for k+8
#define A_U32_TOTAL (2 * 8 * 9 * 4 * 32 * 4)   // 73728

__device__ __align__(16) uint32_t g_qa[A_U32_TOTAL];
__device__ __align__(16) uint32_t g_xh[NN * 64 * HHH * WID];   // half2 planes
__device__ unsigned g_wmax_bits;

// ------------------------- preprocessing ----------------------------------
__global__ void k_init() { g_wmax_bits = 0u; }

__global__ void k_max(const float* __restrict__ w, int n) {
    float m = 0.f;
    for (int i = blockIdx.x * blockDim.x + threadIdx.x; i < n; i += gridDim.x * blockDim.x)
        m = fmaxf(m, fabsf(w[i]));
#pragma unroll
    for (int o = 16; o > 0; o >>= 1) m = fmaxf(m, __shfl_xor_sync(~0u, m, o));
    __shared__ float sm[32];
    int lane = threadIdx.x & 31, wd = threadIdx.x >> 5;
    if (lane == 0) sm[wd] = m;
    __syncthreads();
    if (threadIdx.x < 32) {
        int nw = (blockDim.x + 31) >> 5;
        m = (threadIdx.x < nw) ? sm[threadIdx.x] : 0.f;
#pragma unroll
        for (int o = 16; o > 0; o >>= 1) m = fmaxf(m, __shfl_xor_sync(~0u, m, o));
        if (threadIdx.x == 0) atomicMax(&g_wmax_bits, __float_as_uint(m));
    }
}

// quantize weights into packed byte codes (w+1), fragment order above
__global__ void k_quant(const float* __restrict__ w) {
    int idx = blockIdx.x * blockDim.x + threadIdx.x;
    if (idx >= A_U32_TOTAL) return;
    int q    = idx & 3;
    int lane = (idx >> 2) & 31;
    int mp   = (idx >> 7) & 3;
    int f    = idx >> 9;              // (half*8+chunk)*9 + tap
    int tap  = f % 9;
    int hc   = f / 9;
    int half = hc >> 3, chunk = hc & 7;
    int g = lane >> 2, t4 = lane & 3;
    int mtile = mp * 2 + (q >> 1);
    int khi   = (q & 1) ? 8 : 0;
    float t = 0.05f * __uint_as_float(g_wmax_bits);
    uint32_t out = 0;
#pragma unroll
    for (int b = 0; b < 4; b++) {
        int oc = half * 128 + mtile * 16 + g + 8 * (b >> 1);
        int ic = chunk * 16 + khi + 2 * t4 + (b & 1);
        float wv = w[(oc * CC + ic) * 9 + tap];
        uint32_t code = (uint32_t)((wv > t) - (wv < -t) + 1);
        out |= code << (8 * b);
    }
    g_qa[idx] = out;
}

// x -> channel-pair packed half2 planes, vectorized 4 cols/thread
__global__ void k_xh(const float* __restrict__ x) {
    int idx = blockIdx.x * blockDim.x + threadIdx.x;   // over NN*64*HHH*14
    if (idx >= NN * 64 * HHH * 14) return;
    int c4  = idx % 14;
    int h   = (idx / 14) % HHH;
    int icp = (idx / (14 * HHH)) & 63;
    int n   = idx / (14 * HHH * 64);
    const float* p = x + ((size_t)(n * CC + icp * 2) * HHH + h) * WID + c4 * 4;
    float4 a = *(const float4*)p;
    float4 b = *(const float4*)(p + HHH * WID);
    uint4 o;
    o.x = (uint32_t)__half_as_ushort(__float2half_rn(a.x)) | ((uint32_t)__half_as_ushort(__float2half_rn(b.x)) << 16);
    o.y = (uint32_t)__half_as_ushort(__float2half_rn(a.y)) | ((uint32_t)__half_as_ushort(__float2half_rn(b.y)) << 16);
    o.z = (uint32_t)__half_as_ushort(__float2half_rn(a.z)) | ((uint32_t)__half_as_ushort(__float2half_rn(b.z)) << 16);
    o.w = (uint32_t)__half_as_ushort(__float2half_rn(a.w)) | ((uint32_t)__half_as_ushort(__float2half_rn(b.w)) << 16);
    *(uint4*)(g_xh + ((size_t)(n * 64 + icp) * HHH + h) * WID + c4 * 4) = o;
}

// ------------------------- helpers -----------------------------------------
__device__ __forceinline__ void mma16(float* c, const uint4& a, uint32_t b0, uint32_t b1) {
    asm volatile(
        "mma.sync.aligned.m16n8k16.row.col.f32.f16.f16.f32 "
        "{%0,%1,%2,%3}, {%4,%5,%6,%7}, {%8,%9}, {%0,%1,%2,%3};"
        : "+f"(c[0]), "+f"(c[1]), "+f"(c[2]), "+f"(c[3])
        : "r"(a.x), "r"(a.y), "r"(a.z), "r"(a.w), "r"(b0), "r"(b1));
}

// codes byte b0,b1 -> half2 (w0,w1) exact: (0x6400|c)=1024+c, minus 1025
__device__ __forceinline__ uint32_t xp01(uint32_t c) {
    uint32_t r;
    const uint32_t B64 = 0x64646464u, M = 0xE401E401u;
    asm("prmt.b32 %0, %1, %2, 0x4140;" : "=r"(r) : "r"(c), "r"(B64));
    asm("add.rn.f16x2 %0, %0, %1;" : "+r"(r) : "r"(M));
    return r;
}
__device__ __forceinline__ uint32_t xp23(uint32_t c) {
    uint32_t r;
    const uint32_t B64 = 0x64646464u, M = 0xE401E401u;
    asm("prmt.b32 %0, %1, %2, 0x4342;" : "=r"(r) : "r"(c), "r"(B64));
    asm("add.rn.f16x2 %0, %0, %1;" : "+r"(r) : "r"(M));
    return r;
}

__device__ __forceinline__ uint32_t smem_u32(const void* p) {
    uint32_t a;
    asm("{ .reg .u64 t; cvta.to.shared.u64 t, %1; cvt.u32.u64 %0, t; }" : "=r"(a) : "l"(p));
    return a;
}

__device__ __forceinline__ void cpa16(uint32_t dst, const void* src) {
    asm volatile("cp.async.cg.shared.global [%0], [%1], 16;" :: "r"(dst), "l"(src) : "memory");
}

// issue all cp.async for one ic-chunk into stage buffer at smem addr `sbase`
__device__ __forceinline__ void stage_chunk(uint32_t sbase, int chunk, int half,
                                            int rg, int n, int tid) {
    // A codes: 1152 x 16B, linear, 9 per thread
    const uint4* asrc = (const uint4*)(g_qa + (size_t)(half * 8 + chunk) * (A_BYTES_CHUNK / 4));
#pragma unroll
    for (int i = 0; i < 9; i++) {
        int e = i * NTHR + tid;
        cpa16(sbase + e * 16, asrc + e);
    }
    // B: 8 icpair x 4 rows x 14 x 16B = 448 copies; rows always in-bounds
    const uint32_t bdst = sbase + A_BYTES_CHUNK;
#pragma unroll
    for (int it = 0; it < 4; it++) {
        int i = it * NTHR + tid;
        if (i < 8 * BROWS * 14) {
            int c4  = i % 14;
            int row = (i / 14) % BROWS;
            int icp = i / (14 * BROWS);
            const uint32_t* s = g_xh + ((size_t)(n * 64 + chunk * 8 + icp) * HHH
                                        + (rg * 2 + row)) * WID + c4 * 4;
            cpa16(bdst + (icp * PLX + row * BCOLS + c4 * 4) * 4, s);
        }
    }
    asm volatile("cp.async.commit_group;" ::: "memory");
}

// ------------------------- conv kernel --------------------------------------
// grid (2 oc-halves, 27 row-groups, 32 n), block 128 (warp_m 0..1, warp_n 0..1)
__global__ __launch_bounds__(NTHR, 2) void k_conv(const float* __restrict__ bias,
                                                  float* __restrict__ out) {
    extern __shared__ char smem[];
    const uint32_t sb = smem_u32(smem);

    const int tid    = threadIdx.x;
    const int wid    = tid >> 5;
    const int lane   = tid & 31;
    const int warp_m = wid & 1;       // 64-oc group (4 mtiles = mp warp_m*2, +1)
    const int warp_n = wid >> 1;      // 0..1 output rows
    const int g      = lane >> 2;
    const int t4     = lane & 3;
    const int half   = blockIdx.x;
    const int rg     = blockIdx.y;
    const int n      = blockIdx.z;

    // one-time zero of all B regions (pad cols + plane pad stay zero)
    for (int s = 0; s < NSTAGE; s++) {
        uint32_t* B = (uint32_t*)(smem + s * STAGE_BYTES + A_BYTES_CHUNK);
        for (int i = tid; i < B_WORDS; i += NTHR) B[i] = 0;
    }
    __syncthreads();

    float acc[4][7][4];
#pragma unroll
    for (int mi = 0; mi < 4; mi++)
#pragma unroll
        for (int ni = 0; ni < 7; ni++)
#pragma unroll
            for (int r = 0; r < 4; r++) acc[mi][ni][r] = 0.f;

    stage_chunk(sb, 0, half, rg, n, tid);
    stage_chunk(sb + STAGE_BYTES, 1, half, rg, n, tid);

    for (int chunk = 0; chunk < NCHUNK; chunk++) {
        if (chunk + 1 < NCHUNK)
            asm volatile("cp.async.wait_group 1;" ::: "memory");
        else
            asm volatile("cp.async.wait_group 0;" ::: "memory");
        __syncthreads();
        if (chunk + 2 < NCHUNK)
            stage_chunk(sb + ((chunk + 2) % NSTAGE) * STAGE_BYTES, chunk + 2, half, rg, n, tid);

        const char*     stg = smem + (chunk % NSTAGE) * STAGE_BYTES;
        const uint4*    Ac  = (const uint4*)stg;
        const uint32_t* Bs  = (const uint32_t*)(stg + A_BYTES_CHUNK);
        const uint32_t* Bq0 = Bs + t4 * PLX;          // k pair t4
        const uint32_t* Bq1 = Bs + (t4 + 4) * PLX;    // k pair t4+4

#pragma unroll
        for (int tap = 0; tap < 9; tap++) {
            const int kh = tap / 3, kw = tap - 3 * kh;
            const int prow = (warp_n + kh) * BCOLS + g + kw;
            // 2 x LDS.128: codes for mtiles (2*warp_m .. 2*warp_m+3)
            const uint4 C0 = Ac[(tap * 4 + warp_m * 2) * 32 + lane];
            const uint4 C1 = Ac[(tap * 4 + warp_m * 2 + 1) * 32 + lane];
            uint4 A0, A1, A2, A3;
            A0.x = xp01(C0.x); A0.y = xp23(C0.x); A0.z = xp01(C0.y); A0.w = xp23(C0.y);
            A1.x = xp01(C0.z); A1.y = xp23(C0.z); A1.z = xp01(C0.w); A1.w = xp23(C0.w);
            A2.x = xp01(C1.x); A2.y = xp23(C1.x); A2.z = xp01(C1.y); A2.w = xp23(C1.y);
            A3.x = xp01(C1.z); A3.y = xp23(C1.z); A3.z = xp01(C1.w); A3.w = xp23(C1.w);
            const uint32_t* B0 = Bq0 + prow;
            const uint32_t* B1 = Bq1 + prow;
#pragma unroll
            for (int ni = 0; ni < 7; ni++) {
                uint32_t b0 = B0[ni * 8];
                uint32_t b1 = B1[ni * 8];
                mma16(acc[0][ni], A0, b0, b1);
                mma16(acc[1][ni], A1, b0, b1);
                mma16(acc[2][ni], A2, b0, b1);
                mma16(acc[3][ni], A3, b0, b1);
            }
        }
    }

    // ---- epilogue (oh = rg*2 + warp_n, always < 54)
    const int oh = rg * 2 + warp_n;
#pragma unroll
    for (int mi = 0; mi < 4; mi++) {
        const int oc0 = half * 128 + warp_m * 64 + mi * 16 + g;
        const float bv0 = bias[oc0];
        const float bv1 = bias[oc0 + 8];
        float* o0 = out + ((size_t)n * OCH + oc0) * (OHH * OWW) + oh * OWW;
        float* o1 = o0 + 8 * (OHH * OWW);
#pragma unroll
        for (int ni = 0; ni < 7; ni++) {
            const int ow = ni * 8 + 2 * t4;
            if (ow < OWW) {
                float2 v0 = make_float2(acc[mi][ni][0] + bv0, acc[mi][ni][1] + bv0);
                float2 v1 = make_float2(acc[mi][ni][2] + bv1, acc[mi][ni][3] + bv1);
                *(float2*)(o0 + ow) = v0;
                *(float2*)(o1 + ow) = v1;
            }
        }
    }
}

// ------------------------- launch -------------------------------------------
extern "C" void kernel_launch(void* const* d_in, const int* in_sizes, int n_in,
                              void* d_out, int out_size) {
    const float* x    = (const float*)d_in[0];
    const float* w    = (const float*)d_in[1];
    const float* bias = (const float*)d_in[2];
    float*       out  = (float*)d_out;

    k_init<<<1, 1>>>();
    k_max<<<256, 256>>>(w, OCH * CC * 9);
    k_xh<<<(NN * 64 * HHH * 14 + 255) / 256, 256>>>(x);
    k_quant<<<(A_U32_TOTAL + 255) / 256, 256>>>(w);

    cudaFuncSetAttribute(k_conv, cudaFuncAttributeMaxDynamicSharedMemorySize, SMEM_DYN);
    dim3 grid(2, 27, NN);
    k_conv<<<grid, NTHR, SMEM_DYN>>>(bias, out);

    (void)in_sizes; (void)n_in; (void)out_size;
}